// round 2
// baseline (speedup 1.0000x reference)
#include <cuda_runtime.h>
#include <cuda_bf16.h>
#include <math.h>

// ---------------------------------------------------------------------------
// VectorQuantizerEMA  (sm_103a)
// z:(16,256,32,32) f32, embedding:(4096,256), cluster_size:(4096), embed_avg:(4096,256)
// N = 16384 tokens, n_e = 4096, e_dim = 256
// Output layout (f32, concatenated in reference tuple order):
//   [0]                loss
//   [1 .. +4194304)    z_q (B,C,H,W)
//   [4194305]          perplexity
//   [4194306 +16384)   idx (as float)
//   [4210690 +1048576) new_embedding
//   [5259266 +4096)    new_cluster_size
//   [5263362 +1048576) new_embed_avg
// ---------------------------------------------------------------------------

#define N_TOK   16384
#define N_E     4096
#define E_DIM   256
#define DECAYF  0.99f
#define ONE_M_D 0.01f
#define EPSF    1e-5f
#define BETAF   0.25f

// scratch (allocation-free: __device__ globals)
__device__ int   g_idx[N_TOK];
__device__ float g_enc[N_E];
__device__ float g_esum[N_E * E_DIM];
__device__ float g_enorm[N_E];
__device__ float g_loss;
__device__ float g_smooth[N_E];

// ---------------------------------------------------------------- zero scratch
__global__ void k_zero() {
    int i = blockIdx.x * 256 + threadIdx.x;   // grid 4096 -> 1048576
    g_esum[i] = 0.0f;
    if (i < N_E) g_enc[i] = 0.0f;
    if (i == 0) g_loss = 0.0f;
}

// ------------------------------------------------------- 0.5*||e||^2 per code
__global__ void k_enorm(const float* __restrict__ emb) {
    int w = threadIdx.x >> 5, lane = threadIdx.x & 31;
    int code = blockIdx.x * 8 + w;            // grid 512
    const float* e = emb + code * E_DIM;
    float s = 0.0f;
#pragma unroll
    for (int j = 0; j < 8; ++j) {
        float v = e[lane + j * 32];
        s = fmaf(v, v, s);
    }
#pragma unroll
    for (int off = 16; off > 0; off >>= 1)
        s += __shfl_xor_sync(0xffffffffu, s, off);
    if (lane == 0) g_enorm[code] = 0.5f * s;
}

// ----------------------------------------------------------- argmin (GEMM-ish)
// Block: 64 rows x all 4096 codes. 256 threads, 4x8 micro-tile.
// SMEM: zs full row-panel [256 k][64 m] (64KB) + es chunk [16 k][132] streamed.
#define TM 64
#define TN 128
#define TK 16
#define ESTRIDE 132
#define SM_ARGMIN_BYTES ((256*64 + TK*ESTRIDE) * 4)

__global__ __launch_bounds__(256, 2)
void k_argmin(const float* __restrict__ z, const float* __restrict__ emb,
              float* __restrict__ out_idx_f)
{
    extern __shared__ float sm[];
    float* zs = sm;                    // [256][64]
    float* es = sm + 256 * 64;         // [16][132]
    // reduction arrays overlay zs after compute
    float* red_v = sm;                 // [64][16]
    int*   red_i = (int*)(sm + 64 * 16);

    const int tid = threadIdx.x;
    const int bm  = blockIdx.x;        // 256 blocks of 64 rows
    const int zbase = (bm >> 4) * 262144 + (bm & 15) * 64;

    // load z row-panel: zs[k][m], coalesced float4 along m
    const float* zb = z + zbase;
#pragma unroll
    for (int it = 0; it < 16; ++it) {
        int f4 = tid + it * 256;       // 4096 float4s
        int k  = f4 >> 4;
        int m4 = (f4 & 15) << 2;
        float4 v = *(const float4*)(zb + k * 1024 + m4);
        *(float4*)(zs + k * 64 + m4) = v;
    }
    __syncthreads();

    const int tx = tid & 15;           // 8 codes: tx*4+j and 64+tx*4+j
    const int ty = tid >> 4;           // 4 rows:  ty*4+i
    float bv[4]; int bi[4];
#pragma unroll
    for (int i = 0; i < 4; ++i) { bv[i] = 3.4e38f; bi[i] = 0; }

    for (int n0 = 0; n0 < N_E; n0 += TN) {
        float acc[4][8];
#pragma unroll
        for (int i = 0; i < 4; ++i)
#pragma unroll
            for (int j = 0; j < 8; ++j) acc[i][j] = 0.0f;

        for (int k0 = 0; k0 < E_DIM; k0 += TK) {
            // load e chunk transposed into es[k][n] (coalesced LDG.128 along k)
#pragma unroll
            for (int it = 0; it < 2; ++it) {
                int f4 = tid + it * 256;          // 512 float4s = 128 codes x 16k
                int k4 = (f4 & 3) << 2;
                int nl = f4 >> 2;
                float4 v = *(const float4*)(emb + (n0 + nl) * E_DIM + k0 + k4);
                es[(k4 + 0) * ESTRIDE + nl] = v.x;
                es[(k4 + 1) * ESTRIDE + nl] = v.y;
                es[(k4 + 2) * ESTRIDE + nl] = v.z;
                es[(k4 + 3) * ESTRIDE + nl] = v.w;
            }
            __syncthreads();
#pragma unroll
            for (int k = 0; k < TK; ++k) {
                const float* zrow = zs + (k0 + k) * 64;
                const float* erow = es + k * ESTRIDE;
                float4 a  = *(const float4*)(zrow + (ty << 2));
                float4 b0 = *(const float4*)(erow + (tx << 2));
                float4 b1 = *(const float4*)(erow + 64 + (tx << 2));
                float av[4] = {a.x, a.y, a.z, a.w};
                float bw[8] = {b0.x, b0.y, b0.z, b0.w, b1.x, b1.y, b1.z, b1.w};
#pragma unroll
                for (int i = 0; i < 4; ++i)
#pragma unroll
                    for (int j = 0; j < 8; ++j)
                        acc[i][j] = fmaf(av[i], bw[j], acc[i][j]);
            }
            __syncthreads();
        }
        // score = 0.5||e||^2 - z.e ; keep running min (first index on ties)
#pragma unroll
        for (int j = 0; j < 8; ++j) {
            int ci = n0 + ((j < 4) ? (tx * 4 + j) : (64 + tx * 4 + (j - 4)));
            float h = g_enorm[ci];
#pragma unroll
            for (int i = 0; i < 4; ++i) {
                float s = h - acc[i][j];
                if (s < bv[i] || (s == bv[i] && ci < bi[i])) { bv[i] = s; bi[i] = ci; }
            }
        }
    }

    __syncthreads();  // done with zs; overlay reduction arrays
#pragma unroll
    for (int i = 0; i < 4; ++i) {
        int r = ty * 4 + i;
        red_v[r * 16 + tx] = bv[i];
        red_i[r * 16 + tx] = bi[i];
    }
    __syncthreads();
    if (tid < 64) {
        float best = red_v[tid * 16];
        int besti  = red_i[tid * 16];
#pragma unroll
        for (int t = 1; t < 16; ++t) {
            float v = red_v[tid * 16 + t];
            int  ix = red_i[tid * 16 + t];
            if (v < best || (v == best && ix < besti)) { best = v; besti = ix; }
        }
        int row = bm * 64 + tid;
        g_idx[row] = besti;
        out_idx_f[row] = (float)besti;
    }
}

// ------------------------------------------ gather z_q, loss, EMA scatter sums
__global__ void k_gather(const float* __restrict__ z, const float* __restrict__ emb,
                         float* __restrict__ out_zq)
{
    __shared__ float sred[256];
    int x = blockIdx.x;                 // grid 4096 = 16 b * 256 c
    int c = x & 255, b = x >> 8;
    int tid = threadIdx.x;
    const float* zp = z + b * 262144 + c * 1024;
    float* op = out_zq + b * 262144 + c * 1024;
    float lsum = 0.0f;
    bool do_enc = (c == 0);
#pragma unroll
    for (int l = 0; l < 4; ++l) {
        int hw = tid + l * 256;
        int n = b * 1024 + hw;
        int code = g_idx[n];
        float ev = emb[code * E_DIM + c];
        float zv = zp[hw];
        op[hw] = ev;
        float d = ev - zv;
        lsum = fmaf(d, d, lsum);
        atomicAdd(&g_esum[code * E_DIM + c], zv);
        if (do_enc) atomicAdd(&g_enc[code], 1.0f);
    }
    sred[tid] = lsum;
    __syncthreads();
    for (int s = 128; s > 0; s >>= 1) {
        if (tid < s) sred[tid] += sred[tid + s];
        __syncthreads();
    }
    if (tid == 0) atomicAdd(&g_loss, sred[0]);
}

// --------------------------- finalize scalars, new_cluster_size, smoothed sizes
__global__ void k_final(const float* __restrict__ csz,
                        float* __restrict__ out_cs,
                        float* __restrict__ out_loss,
                        float* __restrict__ out_plex)
{
    __shared__ float s1[1024];
    __shared__ float s2[1024];
    __shared__ float s_n;
    int tid = threadIdx.x;              // 1024 threads, 4 codes each
    float ncs[4];
    float nsum = 0.0f, pl = 0.0f;
#pragma unroll
    for (int r = 0; r < 4; ++r) {
        int code = tid + r * 1024;
        float enc = g_enc[code];
        ncs[r] = csz[code] * DECAYF + ONE_M_D * enc;
        out_cs[code] = ncs[r];
        nsum += ncs[r];
        float p = enc * (1.0f / 16384.0f);
        pl += p * logf(p + 1e-10f);
    }
    s1[tid] = nsum; s2[tid] = pl;
    __syncthreads();
    for (int s = 512; s > 0; s >>= 1) {
        if (tid < s) { s1[tid] += s1[tid + s]; s2[tid] += s2[tid + s]; }
        __syncthreads();
    }
    if (tid == 0) {
        float n = s1[0];
        s_n = n;
        *out_plex = expf(-s2[0]);
        *out_loss = BETAF * g_loss * (1.0f / 4194304.0f);
    }
    __syncthreads();
    float n = s_n;
    float scale = n / (n + (float)N_E * EPSF);
#pragma unroll
    for (int r = 0; r < 4; ++r) {
        int code = tid + r * 1024;
        g_smooth[code] = (ncs[r] + EPSF) * scale;
    }
}

// --------------------------------------- new_embed_avg and new_embedding
__global__ void k_embednew(const float* __restrict__ eavg,
                           float* __restrict__ out_emb,
                           float* __restrict__ out_eavg)
{
    int i = blockIdx.x * 256 + threadIdx.x;   // grid 1024 -> 262144, x4
#pragma unroll
    for (int r = 0; r < 4; ++r) {
        int j = i + r * 262144;
        int code = j >> 8;
        float na = eavg[j] * DECAYF + ONE_M_D * g_esum[j];
        out_eavg[j] = na;
        out_emb[j] = na / g_smooth[code];
    }
}

// ---------------------------------------------------------------------------
extern "C" void kernel_launch(void* const* d_in, const int* in_sizes, int n_in,
                              void* d_out, int out_size)
{
    const float* z    = (const float*)d_in[0];
    const float* emb  = (const float*)d_in[1];
    const float* csz  = (const float*)d_in[2];
    const float* eavg = (const float*)d_in[3];
    float* out = (float*)d_out;

    float* out_loss = out;
    float* out_zq   = out + 1;
    float* out_plex = out + 1 + 4194304;
    float* out_idx  = out_plex + 1;
    float* out_emb  = out_idx + N_TOK;
    float* out_cs   = out_emb + N_E * E_DIM;
    float* out_eavg = out_cs + N_E;

    // capture-safe: attribute set is not a stream operation
    cudaFuncSetAttribute(k_argmin, cudaFuncAttributeMaxDynamicSharedMemorySize,
                         SM_ARGMIN_BYTES);

    k_zero<<<4096, 256>>>();
    k_enorm<<<512, 256>>>(emb);
    k_argmin<<<256, 256, SM_ARGMIN_BYTES>>>(z, emb, out_idx);
    k_gather<<<4096, 256>>>(z, emb, out_zq);
    k_final<<<1, 1024>>>(csz, out_cs, out_loss, out_plex);
    k_embednew<<<1024, 256>>>(eavg, out_emb, out_eavg);
}

// round 7
// speedup vs baseline: 1.7413x; 1.7413x over previous
#include <cuda_runtime.h>
#include <cuda_bf16.h>
#include <math.h>
#include <stdint.h>

// ---------------------------------------------------------------------------
// VectorQuantizerEMA (sm_103a) — mma.sync bf16-split GEMM-argmin (HMMA path)
// ---------------------------------------------------------------------------
#define N_TOK   16384
#define N_E     4096
#define E_DIM   256
#define DECAYF  0.99f
#define ONE_M_D 0.01f
#define EPSF    1e-5f
#define BETAF   0.25f
#define KCAT    768          // 3 * 256 split-K

// ------------------------------------------------- device scratch (no allocs)
__device__ __align__(16) __nv_bfloat16 g_zcat[N_TOK * KCAT]; // [zh | zh | zl]
__device__ __align__(16) __nv_bfloat16 g_ecat[N_E * KCAT];   // [eh | el | eh]
__device__ float g_enorm[N_E];          // 0.5*||e||^2 (fp32 exact)
__device__ int   g_idx[N_TOK];
__device__ float g_t2v1[N_TOK], g_t2v2[N_TOK];
__device__ int   g_t2i1[N_TOK], g_t2i2[N_TOK];
__device__ float g_enc[N_E];
__device__ float g_esum[N_E * E_DIM];
__device__ float g_loss;
__device__ float g_smooth[N_E];

// ---------------------------------------------------------------- ptx helpers
__device__ __forceinline__ uint32_t smem_u32(const void* p) {
    uint32_t r;
    asm("{ .reg .u64 t; cvta.to.shared.u64 t, %1; cvt.u32.u64 %0, t; }"
        : "=r"(r) : "l"(p));
    return r;
}
#define SW128(x) ((x) ^ (((x) >> 3) & 0x70))

#define LDSM_X4(r, a) \
    asm volatile("ldmatrix.sync.aligned.m8n8.x4.shared.b16 {%0,%1,%2,%3}, [%4];" \
        : "=r"((r)[0]), "=r"((r)[1]), "=r"((r)[2]), "=r"((r)[3]) : "r"(a))
#define LDSM_X2(r, a) \
    asm volatile("ldmatrix.sync.aligned.m8n8.x2.shared.b16 {%0,%1}, [%2];" \
        : "=r"((r)[0]), "=r"((r)[1]) : "r"(a))
#define MMA16816(d, a, b) \
    asm volatile("mma.sync.aligned.m16n8k16.row.col.f32.bf16.bf16.f32 " \
        "{%0,%1,%2,%3}, {%4,%5,%6,%7}, {%8,%9}, {%0,%1,%2,%3};" \
        : "+f"((d)[0]), "+f"((d)[1]), "+f"((d)[2]), "+f"((d)[3]) \
        : "r"((a)[0]), "r"((a)[1]), "r"((a)[2]), "r"((a)[3]), \
          "r"((b)[0]), "r"((b)[1]))
#define CP_ASYNC16(dst, src) \
    asm volatile("cp.async.cg.shared.global [%0], [%1], 16;" \
        :: "r"(dst), "l"(src) : "memory")
#define CP_COMMIT()  asm volatile("cp.async.commit_group;" ::: "memory")
#define CP_WAIT0()   asm volatile("cp.async.wait_group 0;" ::: "memory")

__device__ __forceinline__ void upd2(float& v1, int& i1, float& v2, int& i2,
                                     float s, int n) {
    if (s < v1 || (s == v1 && n < i1)) { v2 = v1; i2 = i1; v1 = s; i1 = n; }
    else if (s < v2 || (s == v2 && n < i2)) { v2 = s; i2 = n; }
}

// ---------------------------------------------------------------- zero scratch
__global__ void k_zero() {
    int i = blockIdx.x * 256 + threadIdx.x;   // grid 4096 -> 1048576
    g_esum[i] = 0.0f;
    if (i < N_E) g_enc[i] = 0.0f;
    if (i == 0) g_loss = 0.0f;
}

// --------------------------------------- prep E: split + concat + 0.5||e||^2
__global__ void k_prep_e(const float* __restrict__ emb) {
    __shared__ float sred[256];
    int n = blockIdx.x, c = threadIdx.x;
    float v = emb[n * E_DIM + c];
    __nv_bfloat16 vh = __float2bfloat16_rn(v);
    __nv_bfloat16 vl = __float2bfloat16_rn(v - __bfloat162float(vh));
    g_ecat[n * KCAT + c]       = vh;
    g_ecat[n * KCAT + 256 + c] = vl;
    g_ecat[n * KCAT + 512 + c] = vh;
    sred[c] = v * v;
    __syncthreads();
    for (int s = 128; s > 0; s >>= 1) {
        if (c < s) sred[c] += sred[c + s];
        __syncthreads();
    }
    if (c == 0) g_enorm[n] = 0.5f * sred[0];
}

// --------------------------------- prep Z: transpose (C-major -> token-major)
__global__ void k_prep_z(const float* __restrict__ z) {
    __shared__ float s[32 * 33];
    int blk = blockIdx.x;               // 4096 = 16 b * 8 ctile * 32 hwtile
    int b  = blk >> 8;
    int ct = (blk >> 5) & 7;
    int ht = blk & 31;
    int x = threadIdx.x & 31, y = threadIdx.x >> 5;   // 32 x 8

#pragma unroll
    for (int l = 0; l < 4; ++l) {
        int cin = y * 4 + l;
        int c = ct * 32 + cin;
        s[cin * 33 + x] = z[b * 262144 + c * 1024 + ht * 32 + x];
    }
    __syncthreads();
#pragma unroll
    for (int l = 0; l < 4; ++l) {
        int r = y * 4 + l;                       // local token
        int m = b * 1024 + ht * 32 + r;          // global token
        float v = s[x * 33 + r];
        __nv_bfloat16 vh = __float2bfloat16_rn(v);
        __nv_bfloat16 vl = __float2bfloat16_rn(v - __bfloat162float(vh));
        int c = ct * 32 + x;
        g_zcat[m * KCAT + c]       = vh;
        g_zcat[m * KCAT + 256 + c] = vh;
        g_zcat[m * KCAT + 512 + c] = vl;
    }
}

// --------------------------------------------- mma.sync GEMM + top-2 argmin
// 128 CTAs x 256 thr. CTA = 128 tokens x all 4096 codes, K=768 bf16.
// SMEM: Z panel 12 chunks x [128m x 64k] SW128 (192KB) + E double buf 2x16KB.
#define OFF_Z    0
#define OFF_E0   196608
#define OFF_E1   212992
#define SMEM_MMA 229376

__global__ __launch_bounds__(256, 1) void k_mma() {
    extern __shared__ char smem[];
    uint32_t sb = smem_u32(smem);
    const int tid = threadIdx.x, lane = tid & 31, wid = tid >> 5;
    const int blk = blockIdx.x;
    const int wm = wid & 1;        // 2 M-halves of 64
    const int wn = wid >> 1;       // 4 N-quarters of 32

    // ---- load Z panel (chunk c holds k16 = 8c..8c+7; SW128 within chunk) ----
    {
        const uint4* z4 = ((const uint4*)g_zcat) + (size_t)blk * 128 * 96;
#pragma unroll
        for (int it = 0; it < 48; ++it) {
            int f = it * 256 + tid;          // 12288 uint4
            int m = f / 96, kq = f - m * 96;
            uint4 v = z4[m * 96 + kq];
            uint32_t byte = ((uint32_t)(kq >> 3) << 14) + ((uint32_t)m << 7)
                          + ((uint32_t)(kq & 7) << 4);
            *(uint4*)(smem + OFF_Z + SW128(byte)) = v;
        }
    }
    __syncthreads();

    // per-lane ldmatrix address components
    const int arow = lane & 15, acol = (lane >> 4) << 4;   // A: 16x16 tiles
    const uint32_t aswv = (uint32_t)(arow & 7) << 4;
    const uint32_t abase = sb + OFF_Z + (uint32_t)(wm * 64 + arow) * 128;
    const int brow = lane & 7, bcol = ((lane >> 3) & 1) << 4; // B: 8x16 tiles
    const uint32_t bswv = (uint32_t)brow << 4;
    const uint32_t bbase_off = (uint32_t)(wn * 32 + brow) * 128;

    float v1[8], v2[8]; int i1[8], i2[8];
#pragma unroll
    for (int t = 0; t < 8; ++t) { v1[t] = 3.4e38f; v2[t] = 3.4e38f; i1[t] = 0; i2[t] = 0; }

    for (int nt = 0; nt < 32; ++nt) {
        const int n0 = nt * 128;
        // prologue: chunk 0 -> buf0
        {
            const char* srcb = (const char*)g_ecat + (size_t)n0 * 1536;
#pragma unroll
            for (int i = 0; i < 4; ++i) {
                int f = i * 256 + tid;
                int n = f >> 3, kq = f & 7;
                uint32_t dst = sb + OFF_E0
                    + SW128(((uint32_t)n << 7) + ((uint32_t)kq << 4));
                CP_ASYNC16(dst, srcb + n * 1536 + kq * 16);
            }
            CP_COMMIT(); CP_WAIT0();
        }
        __syncthreads();

        float acc[4][4][4];
#pragma unroll
        for (int am = 0; am < 4; ++am)
#pragma unroll
            for (int bn = 0; bn < 4; ++bn)
#pragma unroll
                for (int q = 0; q < 4; ++q) acc[am][bn][q] = 0.0f;

        for (int c = 0; c < 12; ++c) {
            const uint32_t ebase = (c & 1) ? OFF_E1 : OFF_E0;
            if (c < 11) {   // prefetch next chunk into other buffer
                const char* srcb = (const char*)g_ecat
                    + (size_t)n0 * 1536 + (c + 1) * 128;
                uint32_t dbuf = (c & 1) ? OFF_E0 : OFF_E1;
#pragma unroll
                for (int i = 0; i < 4; ++i) {
                    int f = i * 256 + tid;
                    int n = f >> 3, kq = f & 7;
                    uint32_t dst = sb + dbuf
                        + SW128(((uint32_t)n << 7) + ((uint32_t)kq << 4));
                    CP_ASYNC16(dst, srcb + n * 1536 + kq * 16);
                }
                CP_COMMIT();
            }
            const uint32_t zcb = abase + (uint32_t)c * 16384;
            const uint32_t ecb = sb + ebase + bbase_off;
#pragma unroll
            for (int k16 = 0; k16 < 4; ++k16) {
                uint32_t ar[4][4], br[4][2];
#pragma unroll
                for (int am = 0; am < 4; ++am)
                    LDSM_X4(ar[am], zcb + (uint32_t)(am * 16) * 128
                            + (((uint32_t)(k16 * 32 + acol)) ^ aswv));
#pragma unroll
                for (int bn = 0; bn < 4; ++bn)
                    LDSM_X2(br[bn], ecb + (uint32_t)(bn * 8) * 128
                            + (((uint32_t)(k16 * 32 + bcol)) ^ bswv));
#pragma unroll
                for (int am = 0; am < 4; ++am)
#pragma unroll
                    for (int bn = 0; bn < 4; ++bn)
                        MMA16816(acc[am][bn], ar[am], br[bn]);
            }
            if (c < 11) CP_WAIT0();
            __syncthreads();
        }

        // epilogue: score = 0.5||e||^2 - dot ; update per-lane top2
        const int nbase = n0 + wn * 32 + (lane & 3) * 2;
#pragma unroll
        for (int bn = 0; bn < 4; ++bn) {
            int nc0 = nbase + bn * 8;
            float h0 = __ldg(&g_enorm[nc0]);
            float h1 = __ldg(&g_enorm[nc0 + 1]);
#pragma unroll
            for (int am = 0; am < 4; ++am) {
                upd2(v1[am*2],   i1[am*2],   v2[am*2],   i2[am*2],
                     h0 - acc[am][bn][0], nc0);
                upd2(v1[am*2],   i1[am*2],   v2[am*2],   i2[am*2],
                     h1 - acc[am][bn][1], nc0 + 1);
                upd2(v1[am*2+1], i1[am*2+1], v2[am*2+1], i2[am*2+1],
                     h0 - acc[am][bn][2], nc0);
                upd2(v1[am*2+1], i1[am*2+1], v2[am*2+1], i2[am*2+1],
                     h1 - acc[am][bn][3], nc0 + 1);
            }
        }
    }

    // ---- cross-lane merge via smem (overlay E buffers) ----
    __syncthreads();
    float* sv1 = (float*)(smem + OFF_E0);
    int*   si1 = (int*)  (smem + OFF_E0 + 8192);
    float* sv2 = (float*)(smem + OFF_E0 + 16384);
    int*   si2 = (int*)  (smem + OFF_E0 + 24576);
#pragma unroll
    for (int am = 0; am < 4; ++am)
#pragma unroll
        for (int h = 0; h < 2; ++h) {
            int row = wm * 64 + am * 16 + h * 8 + (lane >> 2);
            int slot = row * 16 + wn * 4 + (lane & 3);
            int t = am * 2 + h;
            sv1[slot] = v1[t]; si1[slot] = i1[t];
            sv2[slot] = v2[t]; si2[slot] = i2[t];
        }
    __syncthreads();
    if (tid < 128) {
        float bv1 = 3.4e38f, bv2 = 3.4e38f; int bi1 = 0, bi2 = 0;
#pragma unroll
        for (int s = 0; s < 16; ++s) {
            int sl = tid * 16 + s;
            upd2(bv1, bi1, bv2, bi2, sv1[sl], si1[sl]);
            upd2(bv1, bi1, bv2, bi2, sv2[sl], si2[sl]);
        }
        int token = blk * 128 + tid;
        g_t2v1[token] = bv1; g_t2i1[token] = bi1;
        g_t2v2[token] = bv2; g_t2i2[token] = bi2;
    }
}

// --------------------------- fixup: exact fp32 rescore of near-tie candidates
__global__ void k_fix(const float* __restrict__ z, const float* __restrict__ emb,
                      float* __restrict__ out_idx_f) {
    int gw = blockIdx.x * 8 + (threadIdx.x >> 5);   // one warp per token
    int lane = threadIdx.x & 31;
    float v1 = g_t2v1[gw], v2 = g_t2v2[gw];
    int i1 = g_t2i1[gw], i2 = g_t2i2[gw];
    int win = i1;
    if (v2 - v1 < 0.05f) {
        int b = gw >> 10, hw = gw & 1023;
        const float* zp = z + b * 262144 + hw;
        const float* e1 = emb + (size_t)i1 * E_DIM;
        const float* e2 = emb + (size_t)i2 * E_DIM;
        float d1 = 0.0f, d2 = 0.0f;
#pragma unroll
        for (int j = 0; j < 8; ++j) {
            int c = lane + j * 32;
            float zv = zp[c * 1024];
            d1 = fmaf(zv, e1[c], d1);
            d2 = fmaf(zv, e2[c], d2);
        }
#pragma unroll
        for (int off = 16; off > 0; off >>= 1) {
            d1 += __shfl_xor_sync(0xffffffffu, d1, off);
            d2 += __shfl_xor_sync(0xffffffffu, d2, off);
        }
        float s1 = g_enorm[i1] - d1;
        float s2 = g_enorm[i2] - d2;
        if (s2 < s1 || (s2 == s1 && i2 < i1)) win = i2;
    }
    if (lane == 0) {
        g_idx[gw] = win;
        out_idx_f[gw] = (float)win;
    }
}

// ------------------------------------------ gather z_q, loss, EMA scatter sums
__global__ void k_gather(const float* __restrict__ z, const float* __restrict__ emb,
                         float* __restrict__ out_zq) {
    __shared__ float sred[256];
    int x = blockIdx.x;                 // grid 4096 = 16 b * 256 c
    int c = x & 255, b = x >> 8;
    int tid = threadIdx.x;
    const float* zp = z + b * 262144 + c * 1024;
    float* op = out_zq + b * 262144 + c * 1024;
    float lsum = 0.0f;
    bool do_enc = (c == 0);
#pragma unroll
    for (int l = 0; l < 4; ++l) {
        int hw = tid + l * 256;
        int n = b * 1024 + hw;
        int code = g_idx[n];
        float ev = emb[code * E_DIM + c];
        float zv = zp[hw];
        op[hw] = ev;
        float d = ev - zv;
        lsum = fmaf(d, d, lsum);
        atomicAdd(&g_esum[code * E_DIM + c], zv);
        if (do_enc) atomicAdd(&g_enc[code], 1.0f);
    }
    sred[tid] = lsum;
    __syncthreads();
    for (int s = 128; s > 0; s >>= 1) {
        if (tid < s) sred[tid] += sred[tid + s];
        __syncthreads();
    }
    if (tid == 0) atomicAdd(&g_loss, sred[0]);
}

// --------------------------- finalize scalars, new_cluster_size, smoothed sizes
__global__ void k_final(const float* __restrict__ csz,
                        float* __restrict__ out_cs,
                        float* __restrict__ out_loss,
                        float* __restrict__ out_plex) {
    __shared__ float s1[1024];
    __shared__ float s2[1024];
    __shared__ float s_n;
    int tid = threadIdx.x;
    float ncs[4];
    float nsum = 0.0f, pl = 0.0f;
#pragma unroll
    for (int r = 0; r < 4; ++r) {
        int code = tid + r * 1024;
        float enc = g_enc[code];
        ncs[r] = csz[code] * DECAYF + ONE_M_D * enc;
        out_cs[code] = ncs[r];
        nsum += ncs[r];
        float p = enc * (1.0f / 16384.0f);
        pl += p * logf(p + 1e-10f);
    }
    s1[tid] = nsum; s2[tid] = pl;
    __syncthreads();
    for (int s = 512; s > 0; s >>= 1) {
        if (tid < s) { s1[tid] += s1[tid + s]; s2[tid] += s2[tid + s]; }
        __syncthreads();
    }
    if (tid == 0) {
        float n = s1[0];
        s_n = n;
        *out_plex = expf(-s2[0]);
        *out_loss = BETAF * g_loss * (1.0f / 4194304.0f);
    }
    __syncthreads();
    float n = s_n;
    float scale = n / (n + (float)N_E * EPSF);
#pragma unroll
    for (int r = 0; r < 4; ++r) {
        int code = tid + r * 1024;
        g_smooth[code] = (ncs[r] + EPSF) * scale;
    }
}

// --------------------------------------- new_embed_avg and new_embedding
__global__ void k_embednew(const float* __restrict__ eavg,
                           float* __restrict__ out_emb,
                           float* __restrict__ out_eavg) {
    int i = blockIdx.x * 256 + threadIdx.x;
#pragma unroll
    for (int r = 0; r < 4; ++r) {
        int j = i + r * 262144;
        int code = j >> 8;
        float na = eavg[j] * DECAYF + ONE_M_D * g_esum[j];
        out_eavg[j] = na;
        out_emb[j] = na / g_smooth[code];
    }
}

// ---------------------------------------------------------------------------
extern "C" void kernel_launch(void* const* d_in, const int* in_sizes, int n_in,
                              void* d_out, int out_size) {
    const float* z    = (const float*)d_in[0];
    const float* emb  = (const float*)d_in[1];
    const float* csz  = (const float*)d_in[2];
    const float* eavg = (const float*)d_in[3];
    float* out = (float*)d_out;

    float* out_loss = out;
    float* out_zq   = out + 1;
    float* out_plex = out + 1 + 4194304;
    float* out_idx  = out_plex + 1;
    float* out_emb  = out_idx + N_TOK;
    float* out_cs   = out_emb + N_E * E_DIM;
    float* out_eavg = out_cs + N_E;

    cudaFuncSetAttribute(k_mma, cudaFuncAttributeMaxDynamicSharedMemorySize,
                         SMEM_MMA);

    k_zero<<<4096, 256>>>();
    k_prep_e<<<N_E, 256>>>(emb);
    k_prep_z<<<4096, 256>>>(z);
    k_mma<<<128, 256, SMEM_MMA>>>();
    k_fix<<<2048, 256>>>(z, emb, out_idx);
    k_gather<<<4096, 256>>>(z, emb, out_zq);
    k_final<<<1, 1024>>>(csz, out_cs, out_loss, out_plex);
    k_embednew<<<1024, 256>>>(eavg, out_emb, out_eavg);
}

// round 11
// speedup vs baseline: 2.2206x; 1.2753x over previous
#include <cuda_runtime.h>
#include <cuda_bf16.h>
#include <math.h>
#include <stdint.h>

// ---------------------------------------------------------------------------
// VectorQuantizerEMA (sm_103a) — mma.sync bf16-split GEMM-argmin, v2b
// 16 warps, dedup Z/E, 4-stage cp.async ring; fixed cross-lane merge slots
// ---------------------------------------------------------------------------
#define N_TOK   16384
#define N_E     4096
#define E_DIM   256
#define DECAYF  0.99f
#define ONE_M_D 0.01f
#define EPSF    1e-5f
#define BETAF   0.25f

// ------------------------------------------------- device scratch (no allocs)
__device__ __align__(16) __nv_bfloat16 g_zcat[N_TOK * 512]; // [zh | zl]
__device__ __align__(16) __nv_bfloat16 g_ecat[N_E * 512];   // [eh | el]
__device__ float g_enorm[N_E];          // 0.5*||e||^2 (fp32 exact)
__device__ int   g_idx[N_TOK];
__device__ float g_t2v1[N_TOK], g_t2v2[N_TOK];
__device__ int   g_t2i1[N_TOK], g_t2i2[N_TOK];
__device__ float g_enc[N_E];
__device__ float g_esum[N_E * E_DIM];
__device__ float g_loss;
__device__ float g_smooth[N_E];

// ---------------------------------------------------------------- ptx helpers
__device__ __forceinline__ uint32_t smem_u32(const void* p) {
    uint32_t r;
    asm("{ .reg .u64 t; cvta.to.shared.u64 t, %1; cvt.u32.u64 %0, t; }"
        : "=r"(r) : "l"(p));
    return r;
}
#define SW128(x) ((x) ^ (((x) >> 3) & 0x70))

#define LDSM_X4(r, a) \
    asm volatile("ldmatrix.sync.aligned.m8n8.x4.shared.b16 {%0,%1,%2,%3}, [%4];" \
        : "=r"((r)[0]), "=r"((r)[1]), "=r"((r)[2]), "=r"((r)[3]) : "r"(a))
#define MMA16816(d, a, b) \
    asm volatile("mma.sync.aligned.m16n8k16.row.col.f32.bf16.bf16.f32 " \
        "{%0,%1,%2,%3}, {%4,%5,%6,%7}, {%8,%9}, {%0,%1,%2,%3};" \
        : "+f"((d)[0]), "+f"((d)[1]), "+f"((d)[2]), "+f"((d)[3]) \
        : "r"((a)[0]), "r"((a)[1]), "r"((a)[2]), "r"((a)[3]), \
          "r"((b)[0]), "r"((b)[1]))
#define CP_ASYNC16(dst, src) \
    asm volatile("cp.async.cg.shared.global [%0], [%1], 16;" \
        :: "r"(dst), "l"(src) : "memory")
#define CP_COMMIT()  asm volatile("cp.async.commit_group;" ::: "memory")
#define CP_WAIT2()   asm volatile("cp.async.wait_group 2;" ::: "memory")

__device__ __forceinline__ void upd2(float& v1, int& i1, float& v2, int& i2,
                                     float s, int n) {
    if (s < v1 || (s == v1 && n < i1)) { v2 = v1; i2 = i1; v1 = s; i1 = n; }
    else if (s < v2 || (s == v2 && n < i2)) { v2 = s; i2 = n; }
}

// ---------------------------------------------------------------- zero scratch
__global__ void k_zero() {
    int i = blockIdx.x * 256 + threadIdx.x;   // grid 4096 -> 1048576
    g_esum[i] = 0.0f;
    if (i < N_E) g_enc[i] = 0.0f;
    if (i == 0) g_loss = 0.0f;
}

// --------------------------------------- prep E: split [eh|el] + 0.5||e||^2
__global__ void k_prep_e(const float* __restrict__ emb) {
    __shared__ float sred[256];
    int n = blockIdx.x, c = threadIdx.x;
    float v = emb[n * E_DIM + c];
    __nv_bfloat16 vh = __float2bfloat16_rn(v);
    __nv_bfloat16 vl = __float2bfloat16_rn(v - __bfloat162float(vh));
    g_ecat[n * 512 + c]       = vh;
    g_ecat[n * 512 + 256 + c] = vl;
    sred[c] = v * v;
    __syncthreads();
    for (int s = 128; s > 0; s >>= 1) {
        if (c < s) sred[c] += sred[c + s];
        __syncthreads();
    }
    if (c == 0) g_enorm[n] = 0.5f * sred[0];
}

// --------------------------------- prep Z: transpose + split [zh|zl]
__global__ void k_prep_z(const float* __restrict__ z) {
    __shared__ float s[32 * 33];
    int blk = blockIdx.x;               // 4096 = 16 b * 8 ctile * 32 hwtile
    int b  = blk >> 8;
    int ct = (blk >> 5) & 7;
    int ht = blk & 31;
    int x = threadIdx.x & 31, y = threadIdx.x >> 5;   // 32 x 8

#pragma unroll
    for (int l = 0; l < 4; ++l) {
        int cin = y * 4 + l;
        int c = ct * 32 + cin;
        s[cin * 33 + x] = z[b * 262144 + c * 1024 + ht * 32 + x];
    }
    __syncthreads();
#pragma unroll
    for (int l = 0; l < 4; ++l) {
        int r = y * 4 + l;                       // local token
        int m = b * 1024 + ht * 32 + r;          // global token
        float v = s[x * 33 + r];
        __nv_bfloat16 vh = __float2bfloat16_rn(v);
        __nv_bfloat16 vl = __float2bfloat16_rn(v - __bfloat162float(vh));
        int c = ct * 32 + x;
        g_zcat[m * 512 + c]       = vh;
        g_zcat[m * 512 + 256 + c] = vl;
    }
}

// --------------------------------------------- mma.sync GEMM + top-2 argmin
// 128 CTAs x 512 thr (16 warps). CTA = 128 tokens x all 4096 codes.
// Logical K = 768 (3-term split) over 12 chunks: c<4: zh*eh, 4-7: zh*el,
// 8-11: zl*eh.  Z panel 8 chunks x 16KB (SW128); E ring 4 stages x 16KB.
#define OFF_Z    0
#define OFF_E    131072
#define SMEM_MMA 196608

__global__ __launch_bounds__(512, 1) void k_mma() {
    extern __shared__ char smem[];
    uint32_t sb = smem_u32(smem);
    const int tid = threadIdx.x, lane = tid & 31, wid = tid >> 5;
    const int blk = blockIdx.x;
    const int wm = wid & 3;        // 4 M-quarters of 32 rows
    const int wn = wid >> 2;       // 4 N-quarters of 32 codes

    // ---- load Z panel: 8 chunks x [128m x 64k] bf16, SW128 within chunk ----
    {
        const uint4* z4 = ((const uint4*)g_zcat) + (size_t)blk * 128 * 64;
#pragma unroll
        for (int it = 0; it < 16; ++it) {
            int f = it * 512 + tid;          // 8192 uint4
            int m = f >> 6, kq = f & 63;
            uint4 v = z4[f];
            uint32_t byte = ((uint32_t)(kq >> 3) << 14) + ((uint32_t)m << 7)
                          + ((uint32_t)(kq & 7) << 4);
            *(uint4*)(smem + OFF_Z + SW128(byte)) = v;
        }
    }
    __syncthreads();

    // A ldmatrix addressing (verified fragment mapping)
    const int arow = lane & 15, acol = (lane >> 4) << 4;
    const uint32_t aswv = (uint32_t)(arow & 7) << 4;
    const uint32_t abase = sb + OFF_Z + (uint32_t)(wm * 32 + arow) * 128;
    // B ldmatrix x4: mats = {n0-7 k0-7, n0-7 k8-15, n8-15 k0-7, n8-15 k8-15}
    const int bg = lane >> 3, brr = lane & 7;
    const uint32_t brow_off = (uint32_t)(brr + ((bg >> 1) << 3)) * 128;
    const uint32_t bswv = (uint32_t)brr << 4;
    const uint32_t bkadd = (uint32_t)(bg & 1) << 4;
    const uint32_t bnbase = (uint32_t)(wn * 32) * 128;

    float v1[4], v2[4]; int i1[4], i2[4];
#pragma unroll
    for (int t = 0; t < 4; ++t) { v1[t] = 3.4e38f; v2[t] = 3.4e38f; i1[t] = 0; i2[t] = 0; }

    for (int nt = 0; nt < 32; ++nt) {
        const int n0 = nt * 128;
        // prologue: prefetch chunks 0,1,2 into stages 0,1,2
#pragma unroll
        for (int pc = 0; pc < 3; ++pc) {
            const char* srcb = (const char*)g_ecat + (size_t)n0 * 1024 + pc * 128;
#pragma unroll
            for (int i = 0; i < 2; ++i) {
                int f = i * 512 + tid;
                int n = f >> 3, kq = f & 7;
                uint32_t dst = sb + OFF_E + (uint32_t)pc * 16384
                    + SW128(((uint32_t)n << 7) + ((uint32_t)kq << 4));
                CP_ASYNC16(dst, srcb + n * 1024 + kq * 16);
            }
            CP_COMMIT();
        }

        float acc[2][4][4];
#pragma unroll
        for (int am = 0; am < 2; ++am)
#pragma unroll
            for (int bn = 0; bn < 4; ++bn)
#pragma unroll
                for (int q = 0; q < 4; ++q) acc[am][bn][q] = 0.0f;

        for (int c = 0; c < 12; ++c) {
            CP_WAIT2();              // oldest of 3 pending groups (chunk c) done
            __syncthreads();         // all warps: chunk c ready, old stage free
            if (c < 9) {             // prefetch chunk c+3 -> stage (c+3)&3
                int ce = (c + 3 < 8) ? (c + 3) : (c - 5);   // e(c+3)
                const char* srcb = (const char*)g_ecat
                    + (size_t)n0 * 1024 + ce * 128;
#pragma unroll
                for (int i = 0; i < 2; ++i) {
                    int f = i * 512 + tid;
                    int n = f >> 3, kq = f & 7;
                    uint32_t dst = sb + OFF_E + (uint32_t)((c + 3) & 3) * 16384
                        + SW128(((uint32_t)n << 7) + ((uint32_t)kq << 4));
                    CP_ASYNC16(dst, srcb + n * 1024 + kq * 16);
                }
            }
            CP_COMMIT();             // empty commit keeps pending count = 3

            const uint32_t za = abase
                + (uint32_t)((c < 8) ? (c & 3) : (c - 4)) * 16384;
            const uint32_t eb = sb + OFF_E + (uint32_t)(c & 3) * 16384 + bnbase;
#pragma unroll
            for (int k16 = 0; k16 < 4; ++k16) {
                uint32_t ar[2][4], brg[2][4];
#pragma unroll
                for (int am = 0; am < 2; ++am)
                    LDSM_X4(ar[am], za + (uint32_t)(am * 16) * 128
                            + (((uint32_t)(k16 * 32 + acol)) ^ aswv));
#pragma unroll
                for (int bt = 0; bt < 2; ++bt)
                    LDSM_X4(brg[bt], eb + (uint32_t)(bt * 16) * 128 + brow_off
                            + (((uint32_t)(k16 * 32 + bkadd)) ^ bswv));
#pragma unroll
                for (int am = 0; am < 2; ++am)
#pragma unroll
                    for (int bt = 0; bt < 2; ++bt) {
                        MMA16816(acc[am][bt * 2],     ar[am], brg[bt]);
                        MMA16816(acc[am][bt * 2 + 1], ar[am], brg[bt] + 2);
                    }
            }
        }

        // epilogue: score = 0.5||e||^2 - dot ; per-lane top2 (regs only)
        const int nb0 = n0 + wn * 32 + (lane & 3) * 2;
#pragma unroll
        for (int bn = 0; bn < 4; ++bn) {
            int nc0 = nb0 + bn * 8;
            float h0 = __ldg(&g_enorm[nc0]);
            float h1 = __ldg(&g_enorm[nc0 + 1]);
#pragma unroll
            for (int am = 0; am < 2; ++am) {
                upd2(v1[am*2],   i1[am*2],   v2[am*2],   i2[am*2],
                     h0 - acc[am][bn][0], nc0);
                upd2(v1[am*2],   i1[am*2],   v2[am*2],   i2[am*2],
                     h1 - acc[am][bn][1], nc0 + 1);
                upd2(v1[am*2+1], i1[am*2+1], v2[am*2+1], i2[am*2+1],
                     h0 - acc[am][bn][2], nc0);
                upd2(v1[am*2+1], i1[am*2+1], v2[am*2+1], i2[am*2+1],
                     h1 - acc[am][bn][3], nc0 + 1);
            }
        }
    }

    // ---- cross-lane merge via smem (overlay E stages; barrier first) ----
    // slot = row*16 + wn*4 + (lane&3): 128 rows x 16 candidates, bijective.
    __syncthreads();
    float* sv1 = (float*)(smem + OFF_E);
    int*   si1 = (int*)  (smem + OFF_E + 8192);
    float* sv2 = (float*)(smem + OFF_E + 16384);
    int*   si2 = (int*)  (smem + OFF_E + 24576);
#pragma unroll
    for (int am = 0; am < 2; ++am)
#pragma unroll
        for (int h = 0; h < 2; ++h) {
            int row = wm * 32 + am * 16 + h * 8 + (lane >> 2);
            int slot = row * 16 + wn * 4 + (lane & 3);
            int t = am * 2 + h;
            sv1[slot] = v1[t]; si1[slot] = i1[t];
            sv2[slot] = v2[t]; si2[slot] = i2[t];
        }
    __syncthreads();
    if (tid < 128) {
        float bv1 = 3.4e38f, bv2 = 3.4e38f; int bi1 = 0, bi2 = 0;
#pragma unroll
        for (int s = 0; s < 16; ++s) {
            int sl = tid * 16 + s;
            upd2(bv1, bi1, bv2, bi2, sv1[sl], si1[sl]);
            upd2(bv1, bi1, bv2, bi2, sv2[sl], si2[sl]);
        }
        int token = blk * 128 + tid;
        g_t2v1[token] = bv1; g_t2i1[token] = bi1;
        g_t2v2[token] = bv2; g_t2i2[token] = bi2;
    }
}

// --------------------------- fixup: exact fp32 rescore of near-tie candidates
__global__ void k_fix(const float* __restrict__ z, const float* __restrict__ emb,
                      float* __restrict__ out_idx_f) {
    int gw = blockIdx.x * 8 + (threadIdx.x >> 5);   // one warp per token
    int lane = threadIdx.x & 31;
    float v1 = g_t2v1[gw], v2 = g_t2v2[gw];
    int i1 = g_t2i1[gw], i2 = g_t2i2[gw];
    int win = i1;
    if (v2 - v1 < 0.05f) {
        int b = gw >> 10, hw = gw & 1023;
        const float* zp = z + b * 262144 + hw;
        const float* e1 = emb + (size_t)i1 * E_DIM;
        const float* e2 = emb + (size_t)i2 * E_DIM;
        float d1 = 0.0f, d2 = 0.0f;
#pragma unroll
        for (int j = 0; j < 8; ++j) {
            int c = lane + j * 32;
            float zv = zp[c * 1024];
            d1 = fmaf(zv, e1[c], d1);
            d2 = fmaf(zv, e2[c], d2);
        }
#pragma unroll
        for (int off = 16; off > 0; off >>= 1) {
            d1 += __shfl_xor_sync(0xffffffffu, d1, off);
            d2 += __shfl_xor_sync(0xffffffffu, d2, off);
        }
        float s1 = g_enorm[i1] - d1;
        float s2 = g_enorm[i2] - d2;
        if (s2 < s1 || (s2 == s1 && i2 < i1)) win = i2;
    }
    if (lane == 0) {
        g_idx[gw] = win;
        out_idx_f[gw] = (float)win;
    }
}

// ------------------------------------------ gather z_q, loss, EMA scatter sums
__global__ void k_gather(const float* __restrict__ z, const float* __restrict__ emb,
                         float* __restrict__ out_zq) {
    __shared__ float sred[256];
    int x = blockIdx.x;                 // grid 4096 = 16 b * 256 c
    int c = x & 255, b = x >> 8;
    int tid = threadIdx.x;
    const float* zp = z + b * 262144 + c * 1024;
    float* op = out_zq + b * 262144 + c * 1024;
    float lsum = 0.0f;
    bool do_enc = (c == 0);
#pragma unroll
    for (int l = 0; l < 4; ++l) {
        int hw = tid + l * 256;
        int n = b * 1024 + hw;
        int code = g_idx[n];
        float ev = emb[code * E_DIM + c];
        float zv = zp[hw];
        op[hw] = ev;
        float d = ev - zv;
        lsum = fmaf(d, d, lsum);
        atomicAdd(&g_esum[code * E_DIM + c], zv);
        if (do_enc) atomicAdd(&g_enc[code], 1.0f);
    }
    sred[tid] = lsum;
    __syncthreads();
    for (int s = 128; s > 0; s >>= 1) {
        if (tid < s) sred[tid] += sred[tid + s];
        __syncthreads();
    }
    if (tid == 0) atomicAdd(&g_loss, sred[0]);
}

// --------------------------- finalize scalars, new_cluster_size, smoothed sizes
__global__ void k_final(const float* __restrict__ csz,
                        float* __restrict__ out_cs,
                        float* __restrict__ out_loss,
                        float* __restrict__ out_plex) {
    __shared__ float s1[1024];
    __shared__ float s2[1024];
    __shared__ float s_n;
    int tid = threadIdx.x;
    float ncs[4];
    float nsum = 0.0f, pl = 0.0f;
#pragma unroll
    for (int r = 0; r < 4; ++r) {
        int code = tid + r * 1024;
        float enc = g_enc[code];
        ncs[r] = csz[code] * DECAYF + ONE_M_D * enc;
        out_cs[code] = ncs[r];
        nsum += ncs[r];
        float p = enc * (1.0f / 16384.0f);
        pl += p * logf(p + 1e-10f);
    }
    s1[tid] = nsum; s2[tid] = pl;
    __syncthreads();
    for (int s = 512; s > 0; s >>= 1) {
        if (tid < s) { s1[tid] += s1[tid + s]; s2[tid] += s2[tid + s]; }
        __syncthreads();
    }
    if (tid == 0) {
        float n = s1[0];
        s_n = n;
        *out_plex = expf(-s2[0]);
        *out_loss = BETAF * g_loss * (1.0f / 4194304.0f);
    }
    __syncthreads();
    float n = s_n;
    float scale = n / (n + (float)N_E * EPSF);
#pragma unroll
    for (int r = 0; r < 4; ++r) {
        int code = tid + r * 1024;
        g_smooth[code] = (ncs[r] + EPSF) * scale;
    }
}

// --------------------------------------- new_embed_avg and new_embedding
__global__ void k_embednew(const float* __restrict__ eavg,
                           float* __restrict__ out_emb,
                           float* __restrict__ out_eavg) {
    int i = blockIdx.x * 256 + threadIdx.x;
#pragma unroll
    for (int r = 0; r < 4; ++r) {
        int j = i + r * 262144;
        int code = j >> 8;
        float na = eavg[j] * DECAYF + ONE_M_D * g_esum[j];
        out_eavg[j] = na;
        out_emb[j] = na / g_smooth[code];
    }
}

// ---------------------------------------------------------------------------
extern "C" void kernel_launch(void* const* d_in, const int* in_sizes, int n_in,
                              void* d_out, int out_size) {
    const float* z    = (const float*)d_in[0];
    const float* emb  = (const float*)d_in[1];
    const float* csz  = (const float*)d_in[2];
    const float* eavg = (const float*)d_in[3];
    float* out = (float*)d_out;

    float* out_loss = out;
    float* out_zq   = out + 1;
    float* out_plex = out + 1 + 4194304;
    float* out_idx  = out_plex + 1;
    float* out_emb  = out_idx + N_TOK;
    float* out_cs   = out_emb + N_E * E_DIM;
    float* out_eavg = out_cs + N_E;

    cudaFuncSetAttribute(k_mma, cudaFuncAttributeMaxDynamicSharedMemorySize,
                         SMEM_MMA);

    k_zero<<<4096, 256>>>();
    k_prep_e<<<N_E, 256>>>(emb);
    k_prep_z<<<4096, 256>>>(z);
    k_mma<<<128, 512, SMEM_MMA>>>();
    k_fix<<<2048, 256>>>(z, emb, out_idx);
    k_gather<<<4096, 256>>>(z, emb, out_zq);
    k_final<<<1, 1024>>>(csz, out_cs, out_loss, out_plex);
    k_embednew<<<1024, 256>>>(eavg, out_emb, out_eavg);
}

// round 16
// speedup vs baseline: 2.4311x; 1.0948x over previous
#include <cuda_runtime.h>
#include <cuda_bf16.h>
#include <math.h>
#include <stdint.h>

// ---------------------------------------------------------------------------
// VectorQuantizerEMA (sm_103a) — mma.sync bf16-split GEMM-argmin, v3
// v2b + warp-staggered k16 + packed top-2 idx + k_zero folded into prep
// ---------------------------------------------------------------------------
#define N_TOK   16384
#define N_E     4096
#define E_DIM   256
#define DECAYF  0.99f
#define ONE_M_D 0.01f
#define EPSF    1e-5f
#define BETAF   0.25f

// ------------------------------------------------- device scratch (no allocs)
__device__ __align__(16) __nv_bfloat16 g_zcat[N_TOK * 512]; // [zh | zl]
__device__ __align__(16) __nv_bfloat16 g_ecat[N_E * 512];   // [eh | el]
__device__ float g_enorm[N_E];          // 0.5*||e||^2 (fp32 exact)
__device__ int   g_idx[N_TOK];
__device__ float g_t2v1[N_TOK], g_t2v2[N_TOK];
__device__ int   g_t2i1[N_TOK], g_t2i2[N_TOK];
__device__ float g_enc[N_E];
__device__ float g_esum[N_E * E_DIM];
__device__ float g_loss;
__device__ float g_smooth[N_E];

// ---------------------------------------------------------------- ptx helpers
__device__ __forceinline__ uint32_t smem_u32(const void* p) {
    uint32_t r;
    asm("{ .reg .u64 t; cvta.to.shared.u64 t, %1; cvt.u32.u64 %0, t; }"
        : "=r"(r) : "l"(p));
    return r;
}
#define SW128(x) ((x) ^ (((x) >> 3) & 0x70))

#define LDSM_X4(r, a) \
    asm volatile("ldmatrix.sync.aligned.m8n8.x4.shared.b16 {%0,%1,%2,%3}, [%4];" \
        : "=r"((r)[0]), "=r"((r)[1]), "=r"((r)[2]), "=r"((r)[3]) : "r"(a))
#define MMA16816(d, a, b) \
    asm volatile("mma.sync.aligned.m16n8k16.row.col.f32.bf16.bf16.f32 " \
        "{%0,%1,%2,%3}, {%4,%5,%6,%7}, {%8,%9}, {%0,%1,%2,%3};" \
        : "+f"((d)[0]), "+f"((d)[1]), "+f"((d)[2]), "+f"((d)[3]) \
        : "r"((a)[0]), "r"((a)[1]), "r"((a)[2]), "r"((a)[3]), \
          "r"((b)[0]), "r"((b)[1]))
#define CP_ASYNC16(dst, src) \
    asm volatile("cp.async.cg.shared.global [%0], [%1], 16;" \
        :: "r"(dst), "l"(src) : "memory")
#define CP_COMMIT()  asm volatile("cp.async.commit_group;" ::: "memory")
#define CP_WAIT2()   asm volatile("cp.async.wait_group 2;" ::: "memory")

// hot-loop top-2: candidates per slot arrive in strictly increasing code
// order, so strict < implements first-index tie-breaking.
__device__ __forceinline__ void upd2p(float& v1, float& v2, uint32_t& i12,
                                      float s, int n) {
    if (s < v1)      { v2 = v1; v1 = s; i12 = ((uint32_t)n << 16) | (i12 >> 16); }
    else if (s < v2) { v2 = s; i12 = (i12 & 0xFFFF0000u) | (uint32_t)n; }
}
// merge-phase top-2 (cross-lane order not monotone: need idx tie-break)
__device__ __forceinline__ void upd2(float& v1, int& i1, float& v2, int& i2,
                                     float s, int n) {
    if (s < v1 || (s == v1 && n < i1)) { v2 = v1; i2 = i1; v1 = s; i1 = n; }
    else if (s < v2 || (s == v2 && n < i2)) { v2 = s; i2 = n; }
}

// ----------------- prep E: zero scratch + split [eh|el] + 0.5||e||^2
__global__ void k_prep_e(const float* __restrict__ emb) {
    __shared__ float sred[256];
    int n = blockIdx.x, c = threadIdx.x;
    g_esum[n * E_DIM + c] = 0.0f;        // block n owns esum row n
    if (c == 0) {
        g_enc[n] = 0.0f;
        if (n == 0) g_loss = 0.0f;
    }
    float v = emb[n * E_DIM + c];
    __nv_bfloat16 vh = __float2bfloat16_rn(v);
    __nv_bfloat16 vl = __float2bfloat16_rn(v - __bfloat162float(vh));
    g_ecat[n * 512 + c]       = vh;
    g_ecat[n * 512 + 256 + c] = vl;
    sred[c] = v * v;
    __syncthreads();
    for (int s = 128; s > 0; s >>= 1) {
        if (c < s) sred[c] += sred[c + s];
        __syncthreads();
    }
    if (c == 0) g_enorm[n] = 0.5f * sred[0];
}

// --------------------------------- prep Z: transpose + split [zh|zl]
__global__ void k_prep_z(const float* __restrict__ z) {
    __shared__ float s[32 * 33];
    int blk = blockIdx.x;               // 4096 = 16 b * 8 ctile * 32 hwtile
    int b  = blk >> 8;
    int ct = (blk >> 5) & 7;
    int ht = blk & 31;
    int x = threadIdx.x & 31, y = threadIdx.x >> 5;   // 32 x 8

#pragma unroll
    for (int l = 0; l < 4; ++l) {
        int cin = y * 4 + l;
        int c = ct * 32 + cin;
        s[cin * 33 + x] = z[b * 262144 + c * 1024 + ht * 32 + x];
    }
    __syncthreads();
#pragma unroll
    for (int l = 0; l < 4; ++l) {
        int r = y * 4 + l;                       // local token
        int m = b * 1024 + ht * 32 + r;          // global token
        float v = s[x * 33 + r];
        __nv_bfloat16 vh = __float2bfloat16_rn(v);
        __nv_bfloat16 vl = __float2bfloat16_rn(v - __bfloat162float(vh));
        int c = ct * 32 + x;
        g_zcat[m * 512 + c]       = vh;
        g_zcat[m * 512 + 256 + c] = vl;
    }
}

// --------------------------------------------- mma.sync GEMM + top-2 argmin
// 128 CTAs x 512 thr (16 warps). CTA = 128 tokens x all 4096 codes.
// Logical K = 768 (3-term split) over 12 chunks: c<4: zh*eh, 4-7: zh*el,
// 8-11: zl*eh.  Z panel 8 chunks x 16KB (SW128); E ring 4 stages x 16KB.
#define OFF_Z    0
#define OFF_E    131072
#define SMEM_MMA 196608

__global__ __launch_bounds__(512, 1) void k_mma() {
    extern __shared__ char smem[];
    uint32_t sb = smem_u32(smem);
    const int tid = threadIdx.x, lane = tid & 31, wid = tid >> 5;
    const int blk = blockIdx.x;
    const int wm = wid & 3;        // 4 M-quarters of 32 rows
    const int wn = wid >> 2;       // 4 N-quarters of 32 codes

    // ---- load Z panel: 8 chunks x [128m x 64k] bf16, SW128 within chunk ----
    {
        const uint4* z4 = ((const uint4*)g_zcat) + (size_t)blk * 128 * 64;
#pragma unroll
        for (int it = 0; it < 16; ++it) {
            int f = it * 512 + tid;          // 8192 uint4
            int m = f >> 6, kq = f & 63;
            uint4 v = z4[f];
            uint32_t byte = ((uint32_t)(kq >> 3) << 14) + ((uint32_t)m << 7)
                          + ((uint32_t)(kq & 7) << 4);
            *(uint4*)(smem + OFF_Z + SW128(byte)) = v;
        }
    }
    __syncthreads();

    // A ldmatrix addressing (verified fragment mapping)
    const int arow = lane & 15, acol = (lane >> 4) << 4;
    const uint32_t aswv = (uint32_t)(arow & 7) << 4;
    const uint32_t abase = sb + OFF_Z + (uint32_t)(wm * 32 + arow) * 128;
    // B ldmatrix x4: mats = {n0-7 k0-7, n0-7 k8-15, n8-15 k0-7, n8-15 k8-15}
    const int bg = lane >> 3, brr = lane & 7;
    const uint32_t brow_off = (uint32_t)(brr + ((bg >> 1) << 3)) * 128;
    const uint32_t bswv = (uint32_t)brr << 4;
    const uint32_t bkadd = (uint32_t)(bg & 1) << 4;
    const uint32_t bnbase = (uint32_t)(wn * 32) * 128;

    float v1[4], v2[4]; uint32_t i12[4];
#pragma unroll
    for (int t = 0; t < 4; ++t) { v1[t] = 3.4e38f; v2[t] = 3.4e38f; i12[t] = 0; }

    for (int nt = 0; nt < 32; ++nt) {
        const int n0 = nt * 128;
        // prologue: prefetch chunks 0,1,2 into stages 0,1,2
#pragma unroll
        for (int pc = 0; pc < 3; ++pc) {
            const char* srcb = (const char*)g_ecat + (size_t)n0 * 1024 + pc * 128;
#pragma unroll
            for (int i = 0; i < 2; ++i) {
                int f = i * 512 + tid;
                int n = f >> 3, kq = f & 7;
                uint32_t dst = sb + OFF_E + (uint32_t)pc * 16384
                    + SW128(((uint32_t)n << 7) + ((uint32_t)kq << 4));
                CP_ASYNC16(dst, srcb + n * 1024 + kq * 16);
            }
            CP_COMMIT();
        }

        float acc[2][4][4];
#pragma unroll
        for (int am = 0; am < 2; ++am)
#pragma unroll
            for (int bn = 0; bn < 4; ++bn)
#pragma unroll
                for (int q = 0; q < 4; ++q) acc[am][bn][q] = 0.0f;

        for (int c = 0; c < 12; ++c) {
            CP_WAIT2();              // oldest of 3 pending groups (chunk c) done
            __syncthreads();         // all warps: chunk c ready, old stage free
            if (c < 9) {             // prefetch chunk c+3 -> stage (c+3)&3
                int ce = (c + 3 < 8) ? (c + 3) : (c - 5);   // e(c+3)
                const char* srcb = (const char*)g_ecat
                    + (size_t)n0 * 1024 + ce * 128;
#pragma unroll
                for (int i = 0; i < 2; ++i) {
                    int f = i * 512 + tid;
                    int n = f >> 3, kq = f & 7;
                    uint32_t dst = sb + OFF_E + (uint32_t)((c + 3) & 3) * 16384
                        + SW128(((uint32_t)n << 7) + ((uint32_t)kq << 4));
                    CP_ASYNC16(dst, srcb + n * 1024 + kq * 16);
                }
            }
            CP_COMMIT();             // empty commit keeps pending count = 3

            const uint32_t za = abase
                + (uint32_t)((c < 8) ? (c & 3) : (c - 4)) * 16384;
            const uint32_t eb = sb + OFF_E + (uint32_t)(c & 3) * 16384 + bnbase;
            // warp-staggered k16 order: breaks post-barrier convoy so the 4
            // warps/SMSP hit LDSM-wait and MMA-issue phases at different times
#pragma unroll
            for (int k16i = 0; k16i < 4; ++k16i) {
                const int k16 = (k16i + wid) & 3;
                uint32_t ar[2][4], brg[2][4];
#pragma unroll
                for (int am = 0; am < 2; ++am)
                    LDSM_X4(ar[am], za + (uint32_t)(am * 16) * 128
                            + (((uint32_t)(k16 * 32 + acol)) ^ aswv));
#pragma unroll
                for (int bt = 0; bt < 2; ++bt)
                    LDSM_X4(brg[bt], eb + (uint32_t)(bt * 16) * 128 + brow_off
                            + (((uint32_t)(k16 * 32 + bkadd)) ^ bswv));
#pragma unroll
                for (int am = 0; am < 2; ++am)
#pragma unroll
                    for (int bt = 0; bt < 2; ++bt) {
                        MMA16816(acc[am][bt * 2],     ar[am], brg[bt]);
                        MMA16816(acc[am][bt * 2 + 1], ar[am], brg[bt] + 2);
                    }
            }
        }

        // epilogue: score = 0.5||e||^2 - dot ; per-lane top2 (regs only)
        const int nb0 = n0 + wn * 32 + (lane & 3) * 2;
#pragma unroll
        for (int bn = 0; bn < 4; ++bn) {
            int nc0 = nb0 + bn * 8;
            float h0 = __ldg(&g_enorm[nc0]);
            float h1 = __ldg(&g_enorm[nc0 + 1]);
#pragma unroll
            for (int am = 0; am < 2; ++am) {
                upd2p(v1[am*2],   v2[am*2],   i12[am*2],
                      h0 - acc[am][bn][0], nc0);
                upd2p(v1[am*2],   v2[am*2],   i12[am*2],
                      h1 - acc[am][bn][1], nc0 + 1);
                upd2p(v1[am*2+1], v2[am*2+1], i12[am*2+1],
                      h0 - acc[am][bn][2], nc0);
                upd2p(v1[am*2+1], v2[am*2+1], i12[am*2+1],
                      h1 - acc[am][bn][3], nc0 + 1);
            }
        }
    }

    // ---- cross-lane merge via smem (overlay E stages; barrier first) ----
    // slot = row*16 + wn*4 + (lane&3): 128 rows x 16 candidates, bijective.
    __syncthreads();
    float* sv1 = (float*)(smem + OFF_E);
    int*   si1 = (int*)  (smem + OFF_E + 8192);
    float* sv2 = (float*)(smem + OFF_E + 16384);
    int*   si2 = (int*)  (smem + OFF_E + 24576);
#pragma unroll
    for (int am = 0; am < 2; ++am)
#pragma unroll
        for (int h = 0; h < 2; ++h) {
            int row = wm * 32 + am * 16 + h * 8 + (lane >> 2);
            int slot = row * 16 + wn * 4 + (lane & 3);
            int t = am * 2 + h;
            sv1[slot] = v1[t]; si1[slot] = (int)(i12[t] >> 16);
            sv2[slot] = v2[t]; si2[slot] = (int)(i12[t] & 0xFFFFu);
        }
    __syncthreads();
    if (tid < 128) {
        float bv1 = 3.4e38f, bv2 = 3.4e38f; int bi1 = 0, bi2 = 0;
#pragma unroll
        for (int s = 0; s < 16; ++s) {
            int sl = tid * 16 + s;
            upd2(bv1, bi1, bv2, bi2, sv1[sl], si1[sl]);
            upd2(bv1, bi1, bv2, bi2, sv2[sl], si2[sl]);
        }
        int token = blk * 128 + tid;
        g_t2v1[token] = bv1; g_t2i1[token] = bi1;
        g_t2v2[token] = bv2; g_t2i2[token] = bi2;
    }
}

// --------------------------- fixup: exact fp32 rescore of near-tie candidates
__global__ void k_fix(const float* __restrict__ z, const float* __restrict__ emb,
                      float* __restrict__ out_idx_f) {
    int gw = blockIdx.x * 8 + (threadIdx.x >> 5);   // one warp per token
    int lane = threadIdx.x & 31;
    float v1 = g_t2v1[gw], v2 = g_t2v2[gw];
    int i1 = g_t2i1[gw], i2 = g_t2i2[gw];
    int win = i1;
    if (v2 - v1 < 0.05f) {
        int b = gw >> 10, hw = gw & 1023;
        const float* zp = z + b * 262144 + hw;
        const float* e1 = emb + (size_t)i1 * E_DIM;
        const float* e2 = emb + (size_t)i2 * E_DIM;
        float d1 = 0.0f, d2 = 0.0f;
#pragma unroll
        for (int j = 0; j < 8; ++j) {
            int c = lane + j * 32;
            float zv = zp[c * 1024];
            d1 = fmaf(zv, e1[c], d1);
            d2 = fmaf(zv, e2[c], d2);
        }
#pragma unroll
        for (int off = 16; off > 0; off >>= 1) {
            d1 += __shfl_xor_sync(0xffffffffu, d1, off);
            d2 += __shfl_xor_sync(0xffffffffu, d2, off);
        }
        float s1 = g_enorm[i1] - d1;
        float s2 = g_enorm[i2] - d2;
        if (s2 < s1 || (s2 == s1 && i2 < i1)) win = i2;
    }
    if (lane == 0) {
        g_idx[gw] = win;
        out_idx_f[gw] = (float)win;
    }
}

// ------------------------------------------ gather z_q, loss, EMA scatter sums
__global__ void k_gather(const float* __restrict__ z, const float* __restrict__ emb,
                         float* __restrict__ out_zq) {
    __shared__ float sred[256];
    int x = blockIdx.x;                 // grid 4096 = 16 b * 256 c
    int c = x & 255, b = x >> 8;
    int tid = threadIdx.x;
    const float* zp = z + b * 262144 + c * 1024;
    float* op = out_zq + b * 262144 + c * 1024;
    float lsum = 0.0f;
    bool do_enc = (c == 0);
#pragma unroll
    for (int l = 0; l < 4; ++l) {
        int hw = tid + l * 256;
        int n = b * 1024 + hw;
        int code = g_idx[n];
        float ev = emb[code * E_DIM + c];
        float zv = zp[hw];
        op[hw] = ev;
        float d = ev - zv;
        lsum = fmaf(d, d, lsum);
        atomicAdd(&g_esum[code * E_DIM + c], zv);
        if (do_enc) atomicAdd(&g_enc[code], 1.0f);
    }
    sred[tid] = lsum;
    __syncthreads();
    for (int s = 128; s > 0; s >>= 1) {
        if (tid < s) sred[tid] += sred[tid + s];
        __syncthreads();
    }
    if (tid == 0) atomicAdd(&g_loss, sred[0]);
}

// --------------------------- finalize scalars, new_cluster_size, smoothed sizes
__global__ void k_final(const float* __restrict__ csz,
                        float* __restrict__ out_cs,
                        float* __restrict__ out_loss,
                        float* __restrict__ out_plex) {
    __shared__ float s1[1024];
    __shared__ float s2[1024];
    __shared__ float s_n;
    int tid = threadIdx.x;
    float ncs[4];
    float nsum = 0.0f, pl = 0.0f;
#pragma unroll
    for (int r = 0; r < 4; ++r) {
        int code = tid + r * 1024;
        float enc = g_enc[code];
        ncs[r] = csz[code] * DECAYF + ONE_M_D * enc;
        out_cs[code] = ncs[r];
        nsum += ncs[r];
        float p = enc * (1.0f / 16384.0f);
        pl += p * logf(p + 1e-10f);
    }
    s1[tid] = nsum; s2[tid] = pl;
    __syncthreads();
    for (int s = 512; s > 0; s >>= 1) {
        if (tid < s) { s1[tid] += s1[tid + s]; s2[tid] += s2[tid + s]; }
        __syncthreads();
    }
    if (tid == 0) {
        float n = s1[0];
        s_n = n;
        *out_plex = expf(-s2[0]);
        *out_loss = BETAF * g_loss * (1.0f / 4194304.0f);
    }
    __syncthreads();
    float n = s_n;
    float scale = n / (n + (float)N_E * EPSF);
#pragma unroll
    for (int r = 0; r < 4; ++r) {
        int code = tid + r * 1024;
        g_smooth[code] = (ncs[r] + EPSF) * scale;
    }
}

// --------------------------------------- new_embed_avg and new_embedding
__global__ void k_embednew(const float* __restrict__ eavg,
                           float* __restrict__ out_emb,
                           float* __restrict__ out_eavg) {
    int i = blockIdx.x * 256 + threadIdx.x;
#pragma unroll
    for (int r = 0; r < 4; ++r) {
        int j = i + r * 262144;
        int code = j >> 8;
        float na = eavg[j] * DECAYF + ONE_M_D * g_esum[j];
        out_eavg[j] = na;
        out_emb[j] = na / g_smooth[code];
    }
}

// ---------------------------------------------------------------------------
extern "C" void kernel_launch(void* const* d_in, const int* in_sizes, int n_in,
                              void* d_out, int out_size) {
    const float* z    = (const float*)d_in[0];
    const float* emb  = (const float*)d_in[1];
    const float* csz  = (const float*)d_in[2];
    const float* eavg = (const float*)d_in[3];
    float* out = (float*)d_out;

    float* out_loss = out;
    float* out_zq   = out + 1;
    float* out_plex = out + 1 + 4194304;
    float* out_idx  = out_plex + 1;
    float* out_emb  = out_idx + N_TOK;
    float* out_cs   = out_emb + N_E * E_DIM;
    float* out_eavg = out_cs + N_E;

    cudaFuncSetAttribute(k_mma, cudaFuncAttributeMaxDynamicSharedMemorySize,
                         SMEM_MMA);

    k_prep_e<<<N_E, 256>>>(emb);
    k_prep_z<<<4096, 256>>>(z);
    k_mma<<<128, 512, SMEM_MMA>>>();
    k_fix<<<2048, 256>>>(z, emb, out_idx);
    k_gather<<<4096, 256>>>(z, emb, out_zq);
    k_final<<<1, 1024>>>(csz, out_cs, out_loss, out_plex);
    k_embednew<<<1024, 256>>>(eavg, out_emb, out_eavg);
}